// round 10
// baseline (speedup 1.0000x reference)
#include <cuda_runtime.h>

#define HW    16384
#define Bn    8
#define Cn    10
#define NP    (Bn*HW)       // 131072 pixels
#define NTH   256
#define NBL   (NP/NTH)      // 512 blocks per pixel-cover
#define NSLOT 32

// Persistent scratch (allocation-free)
__device__ double   g_s1[40*NSLOT];   // BN1 partials: rows 0..19 sum, 20..39 sumsq
__device__ double   g_s2[20*NSLOT];   // BN2 partials
__device__ float    g_p1[40];         // BN1 folded scale/shift
__device__ float    g_p2[20];         // BN2 folded scale/shift
__device__ unsigned g_cnt1, g_cnt2;   // last-block tickets (reset by last block)
__device__ float    g_t1[Bn*2*Cn*HW]; // conv1 pre-BN [b,20,hw]
__device__ float    g_y2[Bn*Cn*HW];   // conv2 pre-BN [b,10,hw]

__device__ __forceinline__ float sigm(float x){ return 1.f/(1.f+__expf(-x)); }
__device__ __forceinline__ float ftanh(float x){ return fmaf(2.f, 1.f/(1.f+__expf(-2.f*x)), -1.f); }

// ============================================================================
// Pass A: grid = 3*NBL.
//   role 0: node0 = ConvGRU(x=h0, h=f0)
//   role 1: comp_att (store) + t1 ch 0..9  + BN1 partials ch 0..9
//   role 2: comp_att (recompute) + t1 ch 10..19 + BN1 partials ch 10..19
// ============================================================================
__global__ void __launch_bounds__(NTH, 5) k_passA(
    const float* __restrict__ f0, const float* __restrict__ h0,
    const float* __restrict__ f1, const float* __restrict__ h1, const float* __restrict__ h2,
    const float* __restrict__ W_att, const float* __restrict__ b_att,
    const float* __restrict__ W_r1,  const float* __restrict__ g_r1, const float* __restrict__ be_r1,
    const float* __restrict__ Wg0, const float* __restrict__ bg0, const float* __restrict__ Wc0,
    float* __restrict__ node0, float* __restrict__ attOut)
{
    __shared__ float2 sWg2[20];        // role 0: gates (40 floats as pairs)
    __shared__ float2 sWc2[100];       // role 0: candidate (200 floats as pairs)
    __shared__ float2 sWatt2[10];      // roles 1/2
    __shared__ float2 sWr2[100];       // roles 1/2: this role's 10 rows of W_r1 (pairs)
    __shared__ float  sT[Cn][NTH];     // roles 1/2 staging (10 KB)
    __shared__ float  sb[3];
    __shared__ double sStat[40];
    __shared__ bool   sLast;

    int tid  = threadIdx.x;
    int lane = tid & 31;
    int w    = tid >> 5;
    int bid  = blockIdx.x & (NBL-1);
    int role = blockIdx.x >> 9;        // 0,1,2

    int idx = bid*NTH + tid;
    int b = idx >> 14, p = idx & (HW-1);
    int base = b*Cn*HW + p;

    if (role == 0){
        for (int i=tid;i<20;i+=NTH)  sWg2[i] = make_float2(Wg0[2*i], Wg0[2*i+1]);
        for (int i=tid;i<100;i+=NTH) sWc2[i] = make_float2(Wc0[2*i], Wc0[2*i+1]);
        if (tid==0){ sb[1]=bg0[0]; sb[2]=bg0[1]; }
        __syncthreads();

        float xv[Cn], hv[Cn];
        #pragma unroll
        for (int c=0;c<Cn;c++){ xv[c]=h0[base+c*HW]; hv[c]=f0[base+c*HW]; }
        float g0=sb[1], g1=sb[2];
        #pragma unroll
        for (int k=0;k<5;k++){
            float2 wx0=sWg2[k],    wh0=sWg2[5+k];     // g0: x rows 0..9, h rows 10..19
            float2 wx1=sWg2[10+k], wh1=sWg2[15+k];    // g1: x rows 20..29, h rows 30..39
            g0 = fmaf(wx0.x, xv[2*k], fmaf(wx0.y, xv[2*k+1], g0));
            g0 = fmaf(wh0.x, hv[2*k], fmaf(wh0.y, hv[2*k+1], g0));
            g1 = fmaf(wx1.x, xv[2*k], fmaf(wx1.y, xv[2*k+1], g1));
            g1 = fmaf(wh1.x, hv[2*k], fmaf(wh1.y, hv[2*k+1], g1));
        }
        float r = sigm(g0), u = sigm(g1);
        #pragma unroll
        for (int o=0;o<Cn;o++){
            float a=0.f;
            #pragma unroll
            for (int k=0;k<5;k++){
                float2 wx=sWc2[o*10+k], wr=sWc2[o*10+5+k];
                a = fmaf(wx.x, xv[2*k], fmaf(wx.y, xv[2*k+1], a));
                a = fmaf(wr.x, r*hv[2*k], fmaf(wr.y, r*hv[2*k+1], a));
            }
            node0[base+o*HW] = (1.f-u)*hv[o] + u*ftanh(a);
        }
        return;
    }

    // ---------------- roles 1 / 2 ----------------
    int half = role - 1;               // 0: ch 0..9, 1: ch 10..19
    for (int i=tid;i<10;i+=NTH) sWatt2[i] = make_float2(W_att[2*i], W_att[2*i+1]);
    for (int i=tid;i<100;i+=NTH){
        int o = i/10, k = i%10;        // local out o, pair k
        int off = (half*10 + o)*20 + 2*k;
        sWr2[i] = make_float2(W_r1[off], W_r1[off+1]);
    }
    if (tid==0) sb[0]=b_att[0];
    __syncthreads();

    float sv[Cn], fv[Cn];
    float ga = sb[0];
    #pragma unroll
    for (int c=0;c<Cn;c++){
        sv[c] = h1[base+c*HW];
        fv[c] = h2[base+c*HW];         // temp: h2
    }
    #pragma unroll
    for (int k=0;k<5;k++){
        float2 w1=sWatt2[k], w2=sWatt2[5+k];
        ga = fmaf(w1.x, sv[2*k], fmaf(w1.y, sv[2*k+1], ga));
        ga = fmaf(w2.x, fv[2*k], fmaf(w2.y, fv[2*k+1], ga));
    }
    float att = sigm(ga);
    if (half==0) attOut[b*HW+p] = att;
    #pragma unroll
    for (int c=0;c<Cn;c++){
        sv[c] = (sv[c]+fv[c])*att;     // (h1+h2)*att
        fv[c] = f1[base+c*HW];
    }
    int tchbase = (b*2*Cn + half*10)*HW + p;
    #pragma unroll
    for (int o=0;o<Cn;o++){
        float t=0.f;
        #pragma unroll
        for (int k=0;k<5;k++){
            float2 wf=sWr2[o*10+k], ws=sWr2[o*10+5+k];
            t = fmaf(wf.x, fv[2*k], fmaf(wf.y, fv[2*k+1], t));
            t = fmaf(ws.x, sv[2*k], fmaf(ws.y, sv[2*k+1], t));
        }
        g_t1[tchbase + o*HW] = t;
        sT[o][tid] = t;
    }
    __syncthreads();

    // warp-per-channel reduction; global ch = half*10 + local
    int slot = bid & (NSLOT-1);
    #pragma unroll
    for (int k=0;k<2;k++){
        int ch = w + k*8;
        if (ch < Cn){
            float s=0.f, q=0.f;
            #pragma unroll
            for (int j=0;j<NTH/32;j++){
                float v = sT[ch][j*32+lane];
                s += v; q = fmaf(v,v,q);
            }
            #pragma unroll
            for (int off=16;off;off>>=1){
                s += __shfl_xor_sync(0xffffffffu,s,off);
                q += __shfl_xor_sync(0xffffffffu,q,off);
            }
            if (lane==0){
                int gch = half*10 + ch;
                atomicAdd(&g_s1[gch*NSLOT+slot],      (double)s);
                atomicAdd(&g_s1[(20+gch)*NSLOT+slot], (double)q);
            }
        }
    }
    __threadfence();
    __syncthreads();
    if (tid==0) sLast = (atomicAdd(&g_cnt1, 1u) == 2*NBL-1);
    __syncthreads();
    if (sLast){
        if (tid<40){
            double s=0.0;
            #pragma unroll
            for (int k=0;k<NSLOT;k++){
                s += __ldcg(&g_s1[tid*NSLOT+k]);
                g_s1[tid*NSLOT+k]=0.0;
            }
            sStat[tid]=s;
        }
        __syncthreads();
        if (tid<20){
            double m = sStat[tid]    * (1.0/(double)NP);
            double v = sStat[20+tid] * (1.0/(double)NP) - m*m;
            float a = g_r1[tid] * rsqrtf((float)v + 1e-5f);
            g_p1[tid]    = a;
            g_p1[20+tid] = be_r1[tid] - (float)(a*m);
        }
        if (tid==0) g_cnt1 = 0u;
    }
}

// ============================================================================
// Pass B: grid = 2*NBL. role h computes y2 outputs h*5..h*5+4 + their BN2 partials.
// ============================================================================
__global__ void __launch_bounds__(NTH, 5) k_passB(
    const float* __restrict__ W_r2, const float* __restrict__ g_r2, const float* __restrict__ be_r2)
{
    __shared__ float2 sW2[50];        // 5 rows x 10 pairs
    __shared__ float  sP[40];
    __shared__ float  sY[5][NTH];     // 5 KB
    __shared__ double sStat[20];
    __shared__ bool   sLast;
    int tid = threadIdx.x;
    int lane = tid & 31;
    int w = tid >> 5;
    int bid  = blockIdx.x & (NBL-1);
    int half = blockIdx.x >> 9;       // 0: out 0..4, 1: out 5..9

    for (int i=tid;i<50;i+=NTH){
        int o = i/10, k = i%10;
        int off = (half*5 + o)*20 + 2*k;
        sW2[i] = make_float2(W_r2[off], W_r2[off+1]);
    }
    if (tid<40) sP[tid]=g_p1[tid];
    __syncthreads();

    int idx = bid*NTH + tid;
    int b = idx >> 14, p = idx & (HW-1);

    float x[2*Cn];
    int tbase = b*2*Cn*HW + p;
    #pragma unroll
    for (int c=0;c<2*Cn;c++){
        float t = g_t1[tbase + c*HW];
        x[c] = fmaxf(fmaf(sP[c], t, sP[20+c]), 0.f);
    }
    int ybase = (b*Cn + half*5)*HW + p;
    #pragma unroll
    for (int o=0;o<5;o++){
        float y=0.f;
        #pragma unroll
        for (int k=0;k<10;k++){
            float2 w2=sW2[o*10+k];
            y = fmaf(w2.x, x[2*k], fmaf(w2.y, x[2*k+1], y));
        }
        g_y2[ybase + o*HW] = y;
        sY[o][tid] = y;
    }
    __syncthreads();

    int slot = bid & (NSLOT-1);
    if (w < 5){
        int ch = w;
        float s=0.f, q=0.f;
        #pragma unroll
        for (int j=0;j<NTH/32;j++){
            float v = sY[ch][j*32+lane];
            s += v; q = fmaf(v,v,q);
        }
        #pragma unroll
        for (int off=16;off;off>>=1){
            s += __shfl_xor_sync(0xffffffffu,s,off);
            q += __shfl_xor_sync(0xffffffffu,q,off);
        }
        if (lane==0){
            int gch = half*5 + ch;
            atomicAdd(&g_s2[gch*NSLOT+slot],      (double)s);
            atomicAdd(&g_s2[(10+gch)*NSLOT+slot], (double)q);
        }
    }
    __threadfence();
    __syncthreads();
    if (tid==0) sLast = (atomicAdd(&g_cnt2, 1u) == 2*NBL-1);
    __syncthreads();
    if (sLast){
        if (tid<20){
            double s=0.0;
            #pragma unroll
            for (int k=0;k<NSLOT;k++){
                s += __ldcg(&g_s2[tid*NSLOT+k]);
                g_s2[tid*NSLOT+k]=0.0;
            }
            sStat[tid]=s;
        }
        __syncthreads();
        if (tid<10){
            double m = sStat[tid]    * (1.0/(double)NP);
            double v = sStat[10+tid] * (1.0/(double)NP) - m*m;
            float a = g_r2[tid] * rsqrtf((float)v + 1e-5f);
            g_p2[tid]    = a;
            g_p2[10+tid] = be_r2[tid] - (float)(a*m);
        }
        if (tid==0) g_cnt2 = 0u;
    }
}

// ============================================================================
// Pass C: grid = 2*NBL. role h: gates (recomputed) + candidate outputs h*5..h*5+4
// ============================================================================
__global__ void __launch_bounds__(NTH, 5) k_passC(
    const float* __restrict__ f1,
    const float* __restrict__ Wg1, const float* __restrict__ bg1, const float* __restrict__ Wc1,
    float* __restrict__ node1)
{
    __shared__ float2 sWg2[20];       // gates pairs
    __shared__ float2 sWc2[50];       // this half's 5 candidate rows (pairs)
    __shared__ float  sP[20], sbg[2];
    int tid = threadIdx.x;
    int bid  = blockIdx.x & (NBL-1);
    int half = blockIdx.x >> 9;

    for (int i=tid;i<20;i+=NTH) sWg2[i] = make_float2(Wg1[2*i], Wg1[2*i+1]);
    for (int i=tid;i<50;i+=NTH){
        int o = i/10, k = i%10;
        int off = (half*5 + o)*20 + 2*k;
        sWc2[i] = make_float2(Wc1[off], Wc1[off+1]);
    }
    if (tid<20) sP[tid]=g_p2[tid];
    if (tid==0){ sbg[0]=bg1[0]; sbg[1]=bg1[1]; }
    __syncthreads();

    int idx = bid*NTH + tid;
    int b = idx >> 14, p = idx & (HW-1);
    int base = b*Cn*HW + p;

    float cf[Cn], fv[Cn];
    #pragma unroll
    for (int o=0;o<Cn;o++){
        float yv = g_y2[base + o*HW];
        cf[o] = fmaxf(fmaf(sP[o], yv, sP[10+o]), 0.f);
        fv[o] = f1[base + o*HW];
    }
    float g0=sbg[0], g1=sbg[1];
    #pragma unroll
    for (int k=0;k<5;k++){
        float2 wx0=sWg2[k],    wh0=sWg2[5+k];
        float2 wx1=sWg2[10+k], wh1=sWg2[15+k];
        g0 = fmaf(wx0.x, cf[2*k], fmaf(wx0.y, cf[2*k+1], g0));
        g0 = fmaf(wh0.x, fv[2*k], fmaf(wh0.y, fv[2*k+1], g0));
        g1 = fmaf(wx1.x, cf[2*k], fmaf(wx1.y, cf[2*k+1], g1));
        g1 = fmaf(wh1.x, fv[2*k], fmaf(wh1.y, fv[2*k+1], g1));
    }
    float r = sigm(g0), u = sigm(g1);
    #pragma unroll
    for (int o=0;o<5;o++){
        float a=0.f;
        #pragma unroll
        for (int k=0;k<5;k++){
            float2 wx=sWc2[o*10+k], wr=sWc2[o*10+5+k];
            a = fmaf(wx.x, cf[2*k], fmaf(wx.y, cf[2*k+1], a));
            a = fmaf(wr.x, r*fv[2*k], fmaf(wr.y, r*fv[2*k+1], a));
        }
        int go = half*5 + o;
        node1[base+go*HW] = (1.f-u)*fv[go] + u*ftanh(a);
    }
}

extern "C" void kernel_launch(void* const* d_in, const int* in_sizes, int n_in,
                              void* d_out, int out_size)
{
    const float* f0    = (const float*)d_in[0];
    const float* f1    = (const float*)d_in[1];
    const float* h0    = (const float*)d_in[2];
    const float* h1    = (const float*)d_in[3];
    const float* h2    = (const float*)d_in[4];
    const float* W_att = (const float*)d_in[5];
    const float* b_att = (const float*)d_in[6];
    const float* W_r1  = (const float*)d_in[7];
    const float* g_r1  = (const float*)d_in[8];
    const float* be_r1 = (const float*)d_in[9];
    const float* W_r2  = (const float*)d_in[10];
    const float* g_r2  = (const float*)d_in[11];
    const float* be_r2 = (const float*)d_in[12];
    const float* Wg0   = (const float*)d_in[13];
    const float* bg0   = (const float*)d_in[14];
    const float* Wc0   = (const float*)d_in[15];
    const float* Wg1   = (const float*)d_in[16];
    const float* bg1   = (const float*)d_in[17];
    const float* Wc1   = (const float*)d_in[18];

    float* out   = (float*)d_out;
    float* node0 = out;                      // [8,10,128,128]
    float* node1 = out + Bn*Cn*HW;           // [8,10,128,128]
    float* att   = out + 2*Bn*Cn*HW;         // [8,1,128,128]

    k_passA<<<3*NBL, NTH>>>(f0, h0, f1, h1, h2, W_att, b_att,
                            W_r1, g_r1, be_r1, Wg0, bg0, Wc0, node0, att);
    k_passB<<<2*NBL, NTH>>>(W_r2, g_r2, be_r2);
    k_passC<<<2*NBL, NTH>>>(f1, Wg1, bg1, Wc1, node1);
}

// round 11
// speedup vs baseline: 1.2064x; 1.2064x over previous
#include <cuda_runtime.h>

#define HW    16384
#define Bn    8
#define Cn    10
#define NP    (Bn*HW)       // 131072 pixels
#define NTH   256
#define NBL   (NP/NTH)      // 512 blocks per pixel-cover
#define NSLOT 32

// Persistent scratch (allocation-free)
__device__ double   g_s1[40*NSLOT];   // BN1 partials: rows 0..19 sum, 20..39 sumsq
__device__ double   g_s2[20*NSLOT];   // BN2 partials
__device__ float    g_p1[40];         // BN1 folded scale/shift
__device__ float    g_p2[20];         // BN2 folded scale/shift
__device__ unsigned g_cnt1, g_cnt2;   // last-block tickets (reset by last block)
__device__ float    g_t1[Bn*2*Cn*HW]; // conv1 pre-BN [b,20,hw]
__device__ float    g_y2[Bn*Cn*HW];   // conv2 pre-BN [b,10,hw]

__device__ __forceinline__ float sigm(float x){ return 1.f/(1.f+__expf(-x)); }
__device__ __forceinline__ float ftanh(float x){ return fmaf(2.f, 1.f/(1.f+__expf(-2.f*x)), -1.f); }

// ===== Pass A: 1024 blocks. Role 0 (bid<512): node0 GRU. Role 1: att + t1 + BN1 stats =====
__global__ void __launch_bounds__(NTH) k_passA(
    const float* __restrict__ f0, const float* __restrict__ h0,
    const float* __restrict__ f1, const float* __restrict__ h1, const float* __restrict__ h2,
    const float* __restrict__ W_att, const float* __restrict__ b_att,
    const float* __restrict__ W_r1,  const float* __restrict__ g_r1, const float* __restrict__ be_r1,
    const float* __restrict__ Wg0, const float* __restrict__ bg0, const float* __restrict__ Wc0,
    float* __restrict__ node0, float* __restrict__ attOut)
{
    __shared__ float2 sWg2[20];         // role 0: gate weight pairs
    __shared__ float2 sWc2[100];        // role 0: candidate weight pairs
    __shared__ float2 sWatt2[10];       // role 1
    __shared__ float2 sWr1_2[200];      // role 1: W_r1 pairs (20 rows x 10 pairs)
    __shared__ float  sT[2*Cn][NTH];    // role 1 staging (20 KB)
    __shared__ float  sb[3];
    __shared__ double sStat[40];
    __shared__ bool   sLast;

    int tid  = threadIdx.x;
    int lane = tid & 31;
    int w    = tid >> 5;
    int bid  = blockIdx.x & (NBL-1);
    int role = blockIdx.x >> 9;

    int idx = bid*NTH + tid;
    int b = idx >> 14, p = idx & (HW-1);
    int base = b*Cn*HW + p;

    if (role == 0){
        // ---------- node0 = ConvGRU(x=h0, h=f0) ----------
        for (int i=tid;i<20;i+=NTH)  sWg2[i] = make_float2(Wg0[2*i], Wg0[2*i+1]);
        for (int i=tid;i<100;i+=NTH) sWc2[i] = make_float2(Wc0[2*i], Wc0[2*i+1]);
        if (tid==0){ sb[1]=bg0[0]; sb[2]=bg0[1]; }
        __syncthreads();

        float xv[Cn], hv[Cn];
        #pragma unroll
        for (int c=0;c<Cn;c++){ xv[c]=h0[base+c*HW]; hv[c]=f0[base+c*HW]; }
        float g0=sb[1], g1=sb[2];
        #pragma unroll
        for (int k=0;k<5;k++){
            float2 wx0=sWg2[k],    wh0=sWg2[5+k];    // g0: x rows 0..9, h rows 10..19
            float2 wx1=sWg2[10+k], wh1=sWg2[15+k];   // g1
            g0 = fmaf(wx0.x, xv[2*k], fmaf(wx0.y, xv[2*k+1], g0));
            g0 = fmaf(wh0.x, hv[2*k], fmaf(wh0.y, hv[2*k+1], g0));
            g1 = fmaf(wx1.x, xv[2*k], fmaf(wx1.y, xv[2*k+1], g1));
            g1 = fmaf(wh1.x, hv[2*k], fmaf(wh1.y, hv[2*k+1], g1));
        }
        float r = sigm(g0), u = sigm(g1);
        float rh[Cn];
        #pragma unroll
        for (int c=0;c<Cn;c++) rh[c] = r*hv[c];
        #pragma unroll
        for (int o=0;o<Cn;o++){
            float a=0.f;
            #pragma unroll
            for (int k=0;k<5;k++){
                float2 wx=sWc2[o*10+k], wr=sWc2[o*10+5+k];
                a = fmaf(wx.x, xv[2*k], fmaf(wx.y, xv[2*k+1], a));
                a = fmaf(wr.x, rh[2*k], fmaf(wr.y, rh[2*k+1], a));
            }
            node0[base+o*HW] = (1.f-u)*hv[o] + u*ftanh(a);
        }
    } else {
        // ---------- comp_att + t1 + BN1 partials ----------
        for (int i=tid;i<10;i+=NTH)  sWatt2[i] = make_float2(W_att[2*i], W_att[2*i+1]);
        for (int i=tid;i<200;i+=NTH){
            int o = i/10, k = i%10;              // row o, pair k
            int off = o*20 + 2*k;
            sWr1_2[i] = make_float2(W_r1[off], W_r1[off+1]);
        }
        if (tid==0) sb[0]=b_att[0];
        __syncthreads();

        float sv[Cn], fv[Cn];
        float ga = sb[0];
        #pragma unroll
        for (int c=0;c<Cn;c++){
            sv[c] = h1[base+c*HW];
            fv[c] = h2[base+c*HW];               // temp: h2
        }
        #pragma unroll
        for (int k=0;k<5;k++){
            float2 w1=sWatt2[k], w2=sWatt2[5+k];
            ga = fmaf(w1.x, sv[2*k], fmaf(w1.y, sv[2*k+1], ga));
            ga = fmaf(w2.x, fv[2*k], fmaf(w2.y, fv[2*k+1], ga));
        }
        float att = sigm(ga);
        attOut[b*HW+p] = att;
        #pragma unroll
        for (int c=0;c<Cn;c++){
            sv[c] = (sv[c]+fv[c])*att;           // (h1+h2)*att
            fv[c] = f1[base+c*HW];
        }
        #pragma unroll
        for (int o=0;o<2*Cn;o++){
            float t=0.f;
            #pragma unroll
            for (int k=0;k<5;k++){
                float2 wf=sWr1_2[o*10+k], ws=sWr1_2[o*10+5+k];
                t = fmaf(wf.x, fv[2*k], fmaf(wf.y, fv[2*k+1], t));
                t = fmaf(ws.x, sv[2*k], fmaf(ws.y, sv[2*k+1], t));
            }
            g_t1[(b*2*Cn+o)*HW + p] = t;
            sT[o][tid] = t;
        }
        __syncthreads();

        // warp-per-channel reduction: warp w handles ch w, w+8, w+16(<20)
        int slot = bid & (NSLOT-1);
        #pragma unroll
        for (int k=0;k<3;k++){
            int ch = w + k*8;
            if (ch < 2*Cn){
                float s=0.f, q=0.f;
                #pragma unroll
                for (int j=0;j<NTH/32;j++){
                    float v = sT[ch][j*32+lane];
                    s += v; q = fmaf(v,v,q);
                }
                #pragma unroll
                for (int off=16;off;off>>=1){
                    s += __shfl_xor_sync(0xffffffffu,s,off);
                    q += __shfl_xor_sync(0xffffffffu,q,off);
                }
                if (lane==0){
                    atomicAdd(&g_s1[ch*NSLOT+slot],      (double)s);
                    atomicAdd(&g_s1[(20+ch)*NSLOT+slot], (double)q);
                }
            }
        }
        __threadfence();
        __syncthreads();
        if (tid==0) sLast = (atomicAdd(&g_cnt1, 1u) == NBL-1);
        __syncthreads();
        if (sLast){
            if (tid<40){
                double s=0.0;
                #pragma unroll
                for (int k=0;k<NSLOT;k++){
                    s += __ldcg(&g_s1[tid*NSLOT+k]);
                    g_s1[tid*NSLOT+k]=0.0;
                }
                sStat[tid]=s;
            }
            __syncthreads();
            if (tid<20){
                double m = sStat[tid]    * (1.0/(double)NP);
                double v = sStat[20+tid] * (1.0/(double)NP) - m*m;
                float a = g_r1[tid] * rsqrtf((float)v + 1e-5f);
                g_p1[tid]    = a;
                g_p1[20+tid] = be_r1[tid] - (float)(a*m);
            }
            if (tid==0) g_cnt1 = 0u;
        }
    }
}

// ===== Pass B: y2 = W_r2 @ relu(bn1(t1)), BN2 partials + last-block fold =====
__global__ void __launch_bounds__(NTH) k_passB(
    const float* __restrict__ W_r2, const float* __restrict__ g_r2, const float* __restrict__ be_r2)
{
    __shared__ float2 sW2[100];        // 10 rows x 10 pairs
    __shared__ float  sP[40];
    __shared__ float  sY[Cn][NTH];     // 10 KB
    __shared__ double sStat[20];
    __shared__ bool   sLast;
    int tid = threadIdx.x;
    int lane = tid & 31;
    int w = tid >> 5;
    for (int i=tid;i<100;i+=NTH) sW2[i] = make_float2(W_r2[2*i], W_r2[2*i+1]);
    if (tid<40) sP[tid]=g_p1[tid];
    __syncthreads();

    int idx = blockIdx.x*NTH + tid;
    int b = idx >> 14, p = idx & (HW-1);

    float x[2*Cn];
    int tbase = b*2*Cn*HW + p;
    #pragma unroll
    for (int c=0;c<2*Cn;c++){
        float t = g_t1[tbase + c*HW];
        x[c] = fmaxf(fmaf(sP[c], t, sP[20+c]), 0.f);
    }
    int ybase = b*Cn*HW + p;
    #pragma unroll
    for (int o=0;o<Cn;o++){
        float y=0.f;
        #pragma unroll
        for (int k=0;k<10;k++){
            float2 w2=sW2[o*10+k];
            y = fmaf(w2.x, x[2*k], fmaf(w2.y, x[2*k+1], y));
        }
        g_y2[ybase + o*HW] = y;
        sY[o][tid] = y;
    }
    __syncthreads();

    // warp-per-channel reduction: warp w handles ch w, and w<2 also ch 8+w
    int slot = blockIdx.x & (NSLOT-1);
    #pragma unroll
    for (int k=0;k<2;k++){
        int ch = w + k*8;
        if (ch < Cn){
            float s=0.f, q=0.f;
            #pragma unroll
            for (int j=0;j<NTH/32;j++){
                float v = sY[ch][j*32+lane];
                s += v; q = fmaf(v,v,q);
            }
            #pragma unroll
            for (int off=16;off;off>>=1){
                s += __shfl_xor_sync(0xffffffffu,s,off);
                q += __shfl_xor_sync(0xffffffffu,q,off);
            }
            if (lane==0){
                atomicAdd(&g_s2[ch*NSLOT+slot],      (double)s);
                atomicAdd(&g_s2[(10+ch)*NSLOT+slot], (double)q);
            }
        }
    }
    __threadfence();
    __syncthreads();
    if (tid==0) sLast = (atomicAdd(&g_cnt2, 1u) == NBL-1);
    __syncthreads();
    if (sLast){
        if (tid<20){
            double s=0.0;
            #pragma unroll
            for (int k=0;k<NSLOT;k++){
                s += __ldcg(&g_s2[tid*NSLOT+k]);
                g_s2[tid*NSLOT+k]=0.0;
            }
            sStat[tid]=s;
        }
        __syncthreads();
        if (tid<10){
            double m = sStat[tid]    * (1.0/(double)NP);
            double v = sStat[10+tid] * (1.0/(double)NP) - m*m;
            float a = g_r2[tid] * rsqrtf((float)v + 1e-5f);
            g_p2[tid]    = a;
            g_p2[10+tid] = be_r2[tid] - (float)(a*m);
        }
        if (tid==0) g_cnt2 = 0u;
    }
}

// ===== Pass C: node1 = ConvGRU(x=relu(bn2(y2)), h=f1) =====
__global__ void __launch_bounds__(NTH) k_passC(
    const float* __restrict__ f1,
    const float* __restrict__ Wg1, const float* __restrict__ bg1, const float* __restrict__ Wc1,
    float* __restrict__ node1)
{
    __shared__ float2 sWg2[20];        // gate pairs
    __shared__ float2 sWc2[100];       // candidate pairs
    __shared__ float  sP[20], sbg[2];
    int tid = threadIdx.x;
    for (int i=tid;i<20;i+=NTH)  sWg2[i] = make_float2(Wg1[2*i], Wg1[2*i+1]);
    for (int i=tid;i<100;i+=NTH) sWc2[i] = make_float2(Wc1[2*i], Wc1[2*i+1]);
    if (tid<20) sP[tid]=g_p2[tid];
    if (tid==0){ sbg[0]=bg1[0]; sbg[1]=bg1[1]; }
    __syncthreads();

    int idx = blockIdx.x*NTH + tid;
    int b = idx >> 14, p = idx & (HW-1);
    int base = b*Cn*HW + p;

    float cf[Cn], fv[Cn];
    #pragma unroll
    for (int o=0;o<Cn;o++){
        float yv = g_y2[base + o*HW];
        cf[o] = fmaxf(fmaf(sP[o], yv, sP[10+o]), 0.f);
        fv[o] = f1[base + o*HW];
    }
    float g0=sbg[0], g1=sbg[1];
    #pragma unroll
    for (int k=0;k<5;k++){
        float2 wx0=sWg2[k],    wh0=sWg2[5+k];
        float2 wx1=sWg2[10+k], wh1=sWg2[15+k];
        g0 = fmaf(wx0.x, cf[2*k], fmaf(wx0.y, cf[2*k+1], g0));
        g0 = fmaf(wh0.x, fv[2*k], fmaf(wh0.y, fv[2*k+1], g0));
        g1 = fmaf(wx1.x, cf[2*k], fmaf(wx1.y, cf[2*k+1], g1));
        g1 = fmaf(wh1.x, fv[2*k], fmaf(wh1.y, fv[2*k+1], g1));
    }
    float r = sigm(g0), u = sigm(g1);
    float rh[Cn];
    #pragma unroll
    for (int c=0;c<Cn;c++) rh[c] = r*fv[c];
    #pragma unroll
    for (int o=0;o<Cn;o++){
        float a=0.f;
        #pragma unroll
        for (int k=0;k<5;k++){
            float2 wx=sWc2[o*10+k], wr=sWc2[o*10+5+k];
            a = fmaf(wx.x, cf[2*k], fmaf(wx.y, cf[2*k+1], a));
            a = fmaf(wr.x, rh[2*k], fmaf(wr.y, rh[2*k+1], a));
        }
        node1[base+o*HW] = (1.f-u)*fv[o] + u*ftanh(a);
    }
}

extern "C" void kernel_launch(void* const* d_in, const int* in_sizes, int n_in,
                              void* d_out, int out_size)
{
    const float* f0    = (const float*)d_in[0];
    const float* f1    = (const float*)d_in[1];
    const float* h0    = (const float*)d_in[2];
    const float* h1    = (const float*)d_in[3];
    const float* h2    = (const float*)d_in[4];
    const float* W_att = (const float*)d_in[5];
    const float* b_att = (const float*)d_in[6];
    const float* W_r1  = (const float*)d_in[7];
    const float* g_r1  = (const float*)d_in[8];
    const float* be_r1 = (const float*)d_in[9];
    const float* W_r2  = (const float*)d_in[10];
    const float* g_r2  = (const float*)d_in[11];
    const float* be_r2 = (const float*)d_in[12];
    const float* Wg0   = (const float*)d_in[13];
    const float* bg0   = (const float*)d_in[14];
    const float* Wc0   = (const float*)d_in[15];
    const float* Wg1   = (const float*)d_in[16];
    const float* bg1   = (const float*)d_in[17];
    const float* Wc1   = (const float*)d_in[18];

    float* out   = (float*)d_out;
    float* node0 = out;                      // [8,10,128,128]
    float* node1 = out + Bn*Cn*HW;           // [8,10,128,128]
    float* att   = out + 2*Bn*Cn*HW;         // [8,1,128,128]

    k_passA<<<2*NBL, NTH>>>(f0, h0, f1, h1, h2, W_att, b_att,
                            W_r1, g_r1, be_r1, Wg0, bg0, Wc0, node0, att);
    k_passB<<<NBL, NTH>>>(W_r2, g_r2, be_r2);
    k_passC<<<NBL, NTH>>>(f1, Wg1, bg1, Wc1, node1);
}